// round 12
// baseline (speedup 1.0000x reference)
#include <cuda_runtime.h>
#include <cuda_fp16.h>
#include <math.h>
#include <stdint.h>

#define NN 30000
#define EE 480000
#define EN (EE + NN)
#define NF 128
#define SLOPE 0.02f
#define NCHUNK ((NN + 255) / 256)   // 118
#define NT ((NN + 127) / 128)       // 235 gemm tiles

// ---------------- scratch (device globals; no allocation allowed) ----------
__device__ int   g_cnt[NN];
__device__ float g_dinv[NN];
__device__ int   g_rowptr[NN + 1];
__device__ int   g_fill[NN];
__device__ int   g_csr_src[EN];
__device__ float g_csr_w[EN];
__device__ float g_bufA[NN * NF];    // fp32 scratch (agg64 out, head proj)
__device__ __half g_bufH[NN * NF];   // fp16 hidden state (pre-activated)
__device__ __half g_bufM[NN * NF];   // fp16 message buffer
__device__ __half g_x16[NN * 64];    // fp16 copy of input x
__device__ int   g_bsum[128];
__device__ unsigned short g_wimg_h[6 * 2 * 16384];
__device__ unsigned short g_wimg_0[2 * 8192];
__device__ int   g_bar_count;
__device__ volatile int g_bar_gen;

// ---------------- helpers ----------------------------------------------------
__device__ __forceinline__ uint32_t smem_u32(const void* p) {
    uint32_t a;
    asm("{ .reg .u64 t; cvta.to.shared.u64 t, %1; cvt.u32.u64 %0, t; }"
        : "=r"(a) : "l"(p));
    return a;
}

#define LDSM_X4(r0, r1, r2, r3, addr) \
    asm volatile("ldmatrix.sync.aligned.m8n8.x4.shared.b16 {%0,%1,%2,%3}, [%4];" \
                 : "=r"(r0), "=r"(r1), "=r"(r2), "=r"(r3) : "r"(addr))

#define MMA16816F16(d, a, b) \
    asm volatile("mma.sync.aligned.m16n8k16.row.col.f32.f16.f16.f32 " \
                 "{%0,%1,%2,%3}, {%4,%5,%6,%7}, {%8,%9}, {%0,%1,%2,%3};" \
                 : "+f"((d)[0]), "+f"((d)[1]), "+f"((d)[2]), "+f"((d)[3]) \
                 : "r"((a)[0]), "r"((a)[1]), "r"((a)[2]), "r"((a)[3]), \
                   "r"((b)[0]), "r"((b)[1]))

__device__ __forceinline__ uint32_t packh2(float a, float b) {
    __half2 h = __floats2half2_rn(a, b);
    return *(uint32_t*)&h;
}
__device__ __forceinline__ float2 h2f2(uint32_t h) {
    __half2 v = *(__half2*)&h;
    return __half22float2(v);
}
__device__ __forceinline__ float lrelu(float v) { return v > 0.f ? v : v * SLOPE; }

__device__ __forceinline__ int edge_at2(const void* ei, int idx, int is64) {
    return is64 ? (int)((const long long*)ei)[idx] : ((const int*)ei)[idx];
}

// device-wide generation barrier (all gridDim.x blocks resident by construction)
__device__ __forceinline__ void grid_barrier() {
    __syncthreads();
    if (threadIdx.x == 0) {
        __threadfence();
        int gen = g_bar_gen;
        if (atomicAdd(&g_bar_count, 1) == (int)gridDim.x - 1) {
            atomicExch(&g_bar_count, 0);
            __threadfence();
            g_bar_gen = gen + 1;
        } else {
            while (g_bar_gen == gen) __nanosleep(32);
        }
        __threadfence();
    }
    __syncthreads();
}

// ---------------- prep item (cnt init + x16 + weight images) ----------------
#define PREP_ITEMS (NN * 32 + 6 * 128 * 16 + 128 * 8 + NN)
__device__ __forceinline__ void prep_item(int idx, const float* x,
                                          const float* Wh, const float* W0) {
    if (idx < NN * 32) {
        float2 v = __ldg((const float2*)(x + 2 * idx));
        ((__half2*)g_x16)[idx] = __floats2half2_rn(v.x, v.y);
        return;
    }
    idx -= NN * 32;
    if (idx < 6 * 128 * 16) {
        int i = idx / (128 * 16);
        int r = idx % (128 * 16);
        int f = r / 16, chunk = r % 16;
        const float* W = Wh + (size_t)i * 16384;
        float v[8], h[8];
        #pragma unroll
        for (int j = 0; j < 8; j++) {
            v[j] = W[(chunk * 8 + j) * 128 + f];
            h[j] = __half2float(__float2half_rn(v[j]));
        }
        uint4 hi = make_uint4(packh2(h[0], h[1]), packh2(h[2], h[3]),
                              packh2(h[4], h[5]), packh2(h[6], h[7]));
        uint4 lo = make_uint4(packh2(v[0]-h[0], v[1]-h[1]), packh2(v[2]-h[2], v[3]-h[3]),
                              packh2(v[4]-h[4], v[5]-h[5]), packh2(v[6]-h[6], v[7]-h[7]));
        int off = f * 256 + ((chunk ^ (f & 7)) << 4);
        char* base = (char*)g_wimg_h + (size_t)i * 65536;
        *(uint4*)(base + off)         = hi;
        *(uint4*)(base + 32768 + off) = lo;
        return;
    }
    idx -= 6 * 128 * 16;
    if (idx < 128 * 8) {
        int f = idx / 8, chunk = idx % 8;
        float v[8], h[8];
        #pragma unroll
        for (int j = 0; j < 8; j++) {
            v[j] = W0[(chunk * 8 + j) * 128 + f];
            h[j] = __half2float(__float2half_rn(v[j]));
        }
        uint4 hi = make_uint4(packh2(h[0], h[1]), packh2(h[2], h[3]),
                              packh2(h[4], h[5]), packh2(h[6], h[7]));
        uint4 lo = make_uint4(packh2(v[0]-h[0], v[1]-h[1]), packh2(v[2]-h[2], v[3]-h[3]),
                              packh2(v[4]-h[4], v[5]-h[5]), packh2(v[6]-h[6], v[7]-h[7]));
        int off = f * 128 + ((chunk ^ (f & 7)) << 4);
        char* base = (char*)g_wimg_0;
        *(uint4*)(base + off)         = hi;
        *(uint4*)(base + 16384 + off) = lo;
        return;
    }
    idx -= 128 * 8;
    if (idx < NN) g_cnt[idx] = 1;   // self-loop
}

// ---------------- gemm phase (device fn, tiles strided over blocks) ---------
// A = fp16 (no split), W = fp16 hi/lo planes: D = A*Wh + A*Wl (fp32 accum).
// Reads of Hin use L2-only loads (rewritten between phases inside this kernel).
template<int K, bool IN16, bool BIAS, bool OUTACT>
__device__ void gemm_phase(const void* __restrict__ Hin,
                           const unsigned short* __restrict__ Wimg,
                           const float* __restrict__ bias,
                           __half* __restrict__ outp, char* smem) {
    constexpr int PITCH  = K * 2;
    constexpr int PBYTES = 128 * PITCH;
    const int tid  = threadIdx.x;
    const int wid  = tid >> 5;
    const int lane = tid & 31;
    const uint32_t sb = smem_u32(smem);

    // stage W once (hi + lo planes)
    {
        const uint4* src = (const uint4*)Wimg;
        uint4* dst = (uint4*)(smem + PBYTES);
        #pragma unroll
        for (int i = tid; i < 2 * PBYTES / 16; i += 256) dst[i] = __ldcg(src + i);
    }
    const int mrow0 = (wid & 3) * 32;
    const int ncol0 = (wid >> 2) * 64;
    const uint32_t aB = sb;
    const uint32_t bOff[2] = {sb + PBYTES, sb + 2 * PBYTES};

    for (int t = blockIdx.x; t < NT; t += gridDim.x) {
        const int node0 = t * 128;
        __syncthreads();   // W staged / prior tile reads done
        {
            constexpr int NCH = K / 8;
            #pragma unroll
            for (int idx = tid; idx < 128 * NCH; idx += 256) {
                int row = idx / NCH;
                int chunk = idx % NCH;
                int node = node0 + row;
                uint4 a16 = make_uint4(0u, 0u, 0u, 0u);
                if (IN16) {
                    if (node < NN)
                        a16 = __ldcg((const uint4*)Hin + (size_t)node * NCH + chunk);
                } else {
                    const float* H = (const float*)Hin;
                    float4 v0 = make_float4(0.f,0.f,0.f,0.f), v1 = v0;
                    if (node < NN) {
                        v0 = __ldcg((const float4*)(H + (size_t)node * K + chunk * 8));
                        v1 = __ldcg((const float4*)(H + (size_t)node * K + chunk * 8 + 4));
                    }
                    a16 = make_uint4(packh2(v0.x, v0.y), packh2(v0.z, v0.w),
                                     packh2(v1.x, v1.y), packh2(v1.z, v1.w));
                }
                int off = row * PITCH + ((chunk ^ (row & 7)) << 4);
                *(uint4*)(smem + off) = a16;
            }
        }
        __syncthreads();

        float acc[2][8][4] = {};
        #pragma unroll
        for (int pt = 0; pt < 2; pt++) {
            const uint32_t bB = bOff[pt];
            #pragma unroll
            for (int ks = 0; ks < K / 16; ks++) {
                uint32_t a[2][4], b[8][2];
                #pragma unroll
                for (int i = 0; i < 2; i++) {
                    int row = mrow0 + i * 16 + (lane & 15);
                    int chunk = ks * 2 + (lane >> 4);
                    uint32_t addr = aB + row * PITCH + ((chunk ^ (row & 7)) << 4);
                    LDSM_X4(a[i][0], a[i][1], a[i][2], a[i][3], addr);
                }
                #pragma unroll
                for (int p = 0; p < 4; p++) {
                    int nrow = ncol0 + p * 16 + (lane >> 4) * 8 + (lane & 7);
                    int chunk = ks * 2 + ((lane >> 3) & 1);
                    uint32_t addr = bB + nrow * PITCH + ((chunk ^ (nrow & 7)) << 4);
                    LDSM_X4(b[2*p][0], b[2*p][1], b[2*p+1][0], b[2*p+1][1], addr);
                }
                #pragma unroll
                for (int i = 0; i < 2; i++)
                    #pragma unroll
                    for (int j = 0; j < 8; j++)
                        MMA16816F16(acc[i][j], a[i], b[j]);
            }
        }

        #pragma unroll
        for (int i = 0; i < 2; i++) {
            #pragma unroll
            for (int j = 0; j < 8; j++) {
                int c = ncol0 + j * 8 + (lane & 3) * 2;
                float2 bb = make_float2(0.f, 0.f);
                if (BIAS) bb = *(const float2*)(bias + c);
                float e0 = acc[i][j][0] + bb.x, e1 = acc[i][j][1] + bb.y;
                float e2 = acc[i][j][2] + bb.x, e3 = acc[i][j][3] + bb.y;
                if (OUTACT) { e0 = lrelu(e0); e1 = lrelu(e1); e2 = lrelu(e2); e3 = lrelu(e3); }
                int r0 = node0 + mrow0 + i * 16 + (lane >> 2);
                int r1 = r0 + 8;
                if (r0 < NN)
                    *(__half2*)(outp + (size_t)r0 * NF + c) = __floats2half2_rn(e0, e1);
                if (r1 < NN)
                    *(__half2*)(outp + (size_t)r1 * NF + c) = __floats2half2_rn(e2, e3);
            }
        }
    }
}

// ---------------- per-node aggregation bodies --------------------------------
__device__ __forceinline__ void agg64_node(int n, int lane) {
    int beg = g_rowptr[n], end = g_rowptr[n + 1];
    const __half2* X = (const __half2*)g_x16;
    float2 acc = make_float2(0.f, 0.f);
    int j = beg;
    for (; j + 7 < end; j += 8) {
        float2 v[8];
        #pragma unroll
        for (int q = 0; q < 8; q++)
            v[q] = __half22float2(__ldg(X + g_csr_src[j + q] * 32 + lane));
        #pragma unroll
        for (int q = 0; q < 8; q++) {
            float w = g_csr_w[j + q];
            acc.x += w * v[q].x; acc.y += w * v[q].y;
        }
    }
    for (; j < end; j++) {
        float w = g_csr_w[j];
        float2 v = __half22float2(__ldg(X + g_csr_src[j] * 32 + lane));
        acc.x += w * v.x; acc.y += w * v.y;
    }
    *(float2*)(g_bufA + (size_t)n * 64 + lane * 2) = acc;
}

__device__ __forceinline__ void agg128_node(int n, int lane, const float* bias) {
    int beg = g_rowptr[n], end = g_rowptr[n + 1];
    const uint2* Tv = (const uint2*)g_bufM;   // rewritten per layer -> L2-only loads
    float4 acc = make_float4(0.f, 0.f, 0.f, 0.f);
    int j = beg;
    for (; j + 7 < end; j += 8) {
        uint2 p[8];
        #pragma unroll
        for (int q = 0; q < 8; q++)
            p[q] = __ldcg(Tv + (size_t)g_csr_src[j + q] * 32 + lane);
        #pragma unroll
        for (int q = 0; q < 8; q++) {
            float w = g_csr_w[j + q];
            float2 a = h2f2(p[q].x), b = h2f2(p[q].y);
            acc.x += w * a.x; acc.y += w * a.y;
            acc.z += w * b.x; acc.w += w * b.y;
        }
    }
    for (; j < end; j++) {
        float w = g_csr_w[j];
        uint2 p = __ldcg(Tv + (size_t)g_csr_src[j] * 32 + lane);
        float2 a = h2f2(p.x), b = h2f2(p.y);
        acc.x += w * a.x; acc.y += w * a.y; acc.z += w * b.x; acc.w += w * b.y;
    }
    float4 bb = __ldg((const float4*)(bias + lane * 4));
    float e0 = lrelu(acc.x + bb.x), e1 = lrelu(acc.y + bb.y);
    float e2 = lrelu(acc.z + bb.z), e3 = lrelu(acc.w + bb.w);
    *(uint2*)(g_bufH + (size_t)n * NF + lane * 4) = make_uint2(packh2(e0, e1), packh2(e2, e3));
}

__device__ __forceinline__ void gemm3_node(int n, int lane, const float* W) {
    uint2 p = __ldcg((const uint2*)g_bufH + (size_t)n * 32 + lane);
    float2 ha = h2f2(p.x), hb = h2f2(p.y);
    float hv[4] = {ha.x, ha.y, hb.x, hb.y};
    float a0 = 0.f, a1 = 0.f, a2 = 0.f;
    #pragma unroll
    for (int j = 0; j < 4; j++) {
        int k = lane * 4 + j;
        a0 += hv[j] * __ldg(W + k * 3 + 0);
        a1 += hv[j] * __ldg(W + k * 3 + 1);
        a2 += hv[j] * __ldg(W + k * 3 + 2);
    }
    #pragma unroll
    for (int o = 16; o > 0; o >>= 1) {
        a0 += __shfl_down_sync(0xffffffffu, a0, o);
        a1 += __shfl_down_sync(0xffffffffu, a1, o);
        a2 += __shfl_down_sync(0xffffffffu, a2, o);
    }
    if (lane == 0) {
        g_bufA[n * 3 + 0] = a0;
        g_bufA[n * 3 + 1] = a1;
        g_bufA[n * 3 + 2] = a2;
    }
}

__device__ __forceinline__ void agg3_node(int n, int lane, const float* bout,
                                          float* out) {
    int beg = g_rowptr[n], end = g_rowptr[n + 1];
    float a0 = 0.f, a1 = 0.f, a2 = 0.f;
    for (int j = beg + lane; j < end; j += 32) {
        int s = g_csr_src[j]; float w = g_csr_w[j];
        a0 += w * __ldcg(g_bufA + s * 3 + 0);
        a1 += w * __ldcg(g_bufA + s * 3 + 1);
        a2 += w * __ldcg(g_bufA + s * 3 + 2);
    }
    #pragma unroll
    for (int o = 16; o > 0; o >>= 1) {
        a0 += __shfl_down_sync(0xffffffffu, a0, o);
        a1 += __shfl_down_sync(0xffffffffu, a1, o);
        a2 += __shfl_down_sync(0xffffffffu, a2, o);
    }
    if (lane == 0) {
        out[n * 3 + 0] = tanhf(a0 + __ldg(bout + 0)) * 0.5f;
        out[n * 3 + 1] = tanhf(a1 + __ldg(bout + 1)) * 0.5f;
        out[n * 3 + 2] = tanhf(a2 + __ldg(bout + 2)) * 0.5f;
    }
}

// ---------------- the persistent mega-kernel ---------------------------------
__global__ void __launch_bounds__(256) k_mega(const float* __restrict__ x,
                                              const void* __restrict__ ei,
                                              const float* __restrict__ W0,
                                              const float* __restrict__ b0,
                                              const float* __restrict__ Wh,
                                              const float* __restrict__ bh,
                                              const float* __restrict__ Wout,
                                              const float* __restrict__ bout,
                                              float* __restrict__ out) {
    extern __shared__ char smem[];
    const int tid  = threadIdx.x;
    const int wid  = tid >> 5;
    const int lane = tid & 31;
    const int nblk = gridDim.x;
    const int nwarp = nblk * 8;
    const int gwarp = blockIdx.x * 8 + wid;

    // dtype sniff (once, before any barrier)
    __shared__ int s64;
    if (tid < 32) {
        const unsigned* w = (const unsigned*)ei;
        unsigned bad = 0;
        for (int i = tid; i < 128; i += 32) bad |= w[2 * i + 1];
        #pragma unroll
        for (int o = 16; o > 0; o >>= 1) bad |= __shfl_xor_sync(0xffffffffu, bad, o);
        if (tid == 0) s64 = (bad == 0u);
    }
    __syncthreads();
    const int is64 = s64;

    // P0: prep (x16 + weight images + cnt=1)
    for (int i = blockIdx.x * 256 + tid; i < PREP_ITEMS; i += nblk * 256)
        prep_item(i, x, Wh, W0);
    grid_barrier();

    // P1: degree count
    for (int e = blockIdx.x * 256 + tid; e < EE; e += nblk * 256)
        atomicAdd(&g_cnt[edge_at2(ei, EE + e, is64)], 1);
    grid_barrier();

    // P2a: per-chunk sums
    if (blockIdx.x < NCHUNK) {
        __shared__ int rsh[8];
        int i = blockIdx.x * 256 + tid;
        int v = (i < NN) ? g_cnt[i] : 0;
        #pragma unroll
        for (int o = 16; o > 0; o >>= 1) v += __shfl_down_sync(0xffffffffu, v, o);
        if (lane == 0) rsh[wid] = v;
        __syncthreads();
        if (tid < 8) {
            int t = rsh[tid];
            #pragma unroll
            for (int o = 4; o > 0; o >>= 1) t += __shfl_down_sync(0xffu, t, o);
            if (tid == 0) g_bsum[blockIdx.x] = t;
        }
    }
    grid_barrier();

    // P2b: scan (rowptr, fill, dinv)
    if (blockIdx.x < NCHUNK) {
        int* sh  = (int*)smem;         // 256 ints
        int* sbs = (int*)smem + 256;   // NCHUNK ints
        __shared__ int s_base;
        if (tid < NCHUNK) sbs[tid] = g_bsum[tid];
        __syncthreads();
        if (tid < 32) {
            int p = 0;
            for (int j = tid; j < (int)blockIdx.x; j += 32) p += sbs[j];
            #pragma unroll
            for (int o = 16; o > 0; o >>= 1) p += __shfl_down_sync(0xffffffffu, p, o);
            if (tid == 0) s_base = p;
        }
        int i = blockIdx.x * 256 + tid;
        int v = (i < NN) ? g_cnt[i] : 0;
        sh[tid] = v;
        __syncthreads();
        #pragma unroll
        for (int d = 1; d < 256; d <<= 1) {
            int a = (tid >= d) ? sh[tid - d] : 0;
            __syncthreads();
            sh[tid] += a;
            __syncthreads();
        }
        if (i < NN) {
            int excl = sh[tid] - v + s_base;
            g_rowptr[i] = excl;
            g_fill[i]   = excl;
            g_dinv[i]   = rsqrtf((float)v);
            if (i == NN - 1) g_rowptr[NN] = excl + v;
        }
    }
    grid_barrier();

    // P3: CSR fill
    for (int e = blockIdx.x * 256 + tid; e < EN; e += nblk * 256) {
        if (e < EE) {
            int s = edge_at2(ei, e, is64);
            int d = edge_at2(ei, EE + e, is64);
            int pos = atomicAdd(&g_fill[d], 1);
            g_csr_src[pos] = s;
            g_csr_w[pos]   = g_dinv[s] * g_dinv[d];
        } else {
            int i = e - EE;
            int pos = atomicAdd(&g_fill[i], 1);
            float di = g_dinv[i];
            g_csr_src[pos] = i;
            g_csr_w[pos]   = di * di;
        }
    }
    grid_barrier();

    // P4: agg64 (A = aggregate of x16)
    for (int n = gwarp; n < NN; n += nwarp) agg64_node(n, lane);
    grid_barrier();

    // P5: gemm64 -> H16 = leaky((A x) @ W0 + b0)
    gemm_phase<64, false, true, true>(g_bufA, g_wimg_0, b0, g_bufH, smem);
    grid_barrier();

    // 6 hidden layers
    for (int l = 0; l < 6; l++) {
        gemm_phase<128, true, false, false>(g_bufH, g_wimg_h + (size_t)l * 32768,
                                            nullptr, g_bufM, smem);
        grid_barrier();
        const float* bias = bh + (size_t)l * NF;
        for (int n = gwarp; n < NN; n += nwarp) agg128_node(n, lane, bias);
        grid_barrier();
    }

    // head: P = H16 @ Wout  (into g_bufA, 3 floats/node)
    for (int n = gwarp; n < NN; n += nwarp) gemm3_node(n, lane, Wout);
    grid_barrier();

    // out = tanh(A P + bout) * 0.5
    for (int n = gwarp; n < NN; n += nwarp) agg3_node(n, lane, bout, out);
}

// ---------------- launch -----------------------------------------------------
extern "C" void kernel_launch(void* const* d_in, const int* in_sizes, int n_in,
                              void* d_out, int out_size) {
    const float* x    = (const float*)d_in[0];
    const void*  ei   = d_in[1];
    const float* W0   = (const float*)d_in[2];
    const float* b0   = (const float*)d_in[3];
    const float* Wh   = (const float*)d_in[4];
    const float* bh   = (const float*)d_in[5];
    const float* Wout = (const float*)d_in[6];
    const float* bout = (const float*)d_in[7];
    float* out = (float*)d_out;

    const int SMEM = 3 * 128 * 128 * 2;  // 96 KB
    static int configured = 0;
    if (!configured) {
        cudaFuncSetAttribute(k_mega, cudaFuncAttributeMaxDynamicSharedMemorySize, SMEM);
        configured = 1;
    }
    int nsm = 148;
    cudaDeviceGetAttribute(&nsm, cudaDevAttrMultiProcessorCount, 0);

    k_mega<<<nsm, 256, SMEM>>>(x, ei, W0, b0, Wh, bh, Wout, bout, out);
}

// round 13
// speedup vs baseline: 2.1845x; 2.1845x over previous
#include <cuda_runtime.h>
#include <cuda_fp16.h>
#include <math.h>
#include <stdint.h>

#define NN 30000
#define EE 480000
#define EN (EE + NN)
#define NF 128
#define SLOPE 0.02f

// ---------------- scratch (device globals; no allocation allowed) ----------
__device__ int   g_cnt[NN];
__device__ float g_dinv[NN];
__device__ int   g_rowptr[NN + 1];
__device__ int   g_fill[NN];
__device__ int   g_csr_src[EN];
__device__ float g_csr_w[EN];
__device__ float g_bufA[NN * NF];    // fp32 scratch (agg64 out, head proj P)
__device__ __half g_bufH[NN * NF];   // fp16 hidden state (pre-activated)
__device__ __half g_bufM[NN * NF];   // fp16 message buffer (gathered operand)
__device__ __half g_x16[NN * 64];    // fp16 copy of input x
__device__ int   g_bsum[128];
// pre-imaged weights (exact swizzled smem byte layout), fp16 hi/lo planes.
__device__ unsigned short g_wimg_h[6 * 2 * 16384];
__device__ unsigned short g_wimg_0[2 * 8192];

// ---------------- mma/ldmatrix helpers (plain sm_103-safe PTX) -------------
__device__ __forceinline__ uint32_t smem_u32(const void* p) {
    uint32_t a;
    asm("{ .reg .u64 t; cvta.to.shared.u64 t, %1; cvt.u32.u64 %0, t; }"
        : "=r"(a) : "l"(p));
    return a;
}

#define LDSM_X4(r0, r1, r2, r3, addr) \
    asm volatile("ldmatrix.sync.aligned.m8n8.x4.shared.b16 {%0,%1,%2,%3}, [%4];" \
                 : "=r"(r0), "=r"(r1), "=r"(r2), "=r"(r3) : "r"(addr))

#define MMA16816F16(d, a, b) \
    asm volatile("mma.sync.aligned.m16n8k16.row.col.f32.f16.f16.f32 " \
                 "{%0,%1,%2,%3}, {%4,%5,%6,%7}, {%8,%9}, {%0,%1,%2,%3};" \
                 : "+f"((d)[0]), "+f"((d)[1]), "+f"((d)[2]), "+f"((d)[3]) \
                 : "r"((a)[0]), "r"((a)[1]), "r"((a)[2]), "r"((a)[3]), \
                   "r"((b)[0]), "r"((b)[1]))

__device__ __forceinline__ uint32_t packh2(float a, float b) {
    __half2 h = __floats2half2_rn(a, b);
    return *(uint32_t*)&h;
}
__device__ __forceinline__ float2 h2f2(uint32_t h) {
    __half2 v = *(__half2*)&h;
    return __half22float2(v);
}
__device__ __forceinline__ float lrelu(float v) { return v > 0.f ? v : v * SLOPE; }

// per-block inline dtype sniff: int64 edges < 2^31 => odd words of first 128 are 0
__device__ __forceinline__ int sniff_is64(const void* ei, int* s_flag) {
    if (threadIdx.x < 32) {
        const unsigned* w = (const unsigned*)ei;
        unsigned bad = 0;
        for (int i = threadIdx.x; i < 128; i += 32) bad |= w[2 * i + 1];
        #pragma unroll
        for (int o = 16; o > 0; o >>= 1) bad |= __shfl_xor_sync(0xffffffffu, bad, o);
        if (threadIdx.x == 0) *s_flag = (bad == 0u);
    }
    __syncthreads();
    return *s_flag;
}

__device__ __forceinline__ int edge_at2(const void* ei, int idx, int is64) {
    return is64 ? (int)((const long long*)ei)[idx] : ((const int*)ei)[idx];
}

// ---------------- merged prep: cnt init + x16 + weight images ---------------
__global__ void k_prep(const float* __restrict__ x, const float* __restrict__ Wh,
                       const float* __restrict__ W0) {
    int idx = blockIdx.x * 256 + threadIdx.x;
    if (idx < NN * 32) {
        float2 v = __ldg((const float2*)(x + 2 * idx));
        ((__half2*)g_x16)[idx] = __floats2half2_rn(v.x, v.y);
        return;
    }
    idx -= NN * 32;
    if (idx < 6 * 128 * 16) {
        int i = idx / (128 * 16);
        int r = idx % (128 * 16);
        int f = r / 16;
        int chunk = r % 16;
        const float* W = Wh + (size_t)i * 16384;
        float v[8], h[8];
        #pragma unroll
        for (int j = 0; j < 8; j++) {
            v[j] = W[(chunk * 8 + j) * 128 + f];
            h[j] = __half2float(__float2half_rn(v[j]));
        }
        uint4 hi = make_uint4(packh2(h[0], h[1]), packh2(h[2], h[3]),
                              packh2(h[4], h[5]), packh2(h[6], h[7]));
        uint4 lo = make_uint4(packh2(v[0]-h[0], v[1]-h[1]), packh2(v[2]-h[2], v[3]-h[3]),
                              packh2(v[4]-h[4], v[5]-h[5]), packh2(v[6]-h[6], v[7]-h[7]));
        int off = f * 256 + ((chunk ^ (f & 7)) << 4);
        char* base = (char*)g_wimg_h + (size_t)i * 65536;
        *(uint4*)(base + off)         = hi;
        *(uint4*)(base + 32768 + off) = lo;
        return;
    }
    idx -= 6 * 128 * 16;
    if (idx < 128 * 8) {
        int f = idx / 8;
        int chunk = idx % 8;
        float v[8], h[8];
        #pragma unroll
        for (int j = 0; j < 8; j++) {
            v[j] = W0[(chunk * 8 + j) * 128 + f];
            h[j] = __half2float(__float2half_rn(v[j]));
        }
        uint4 hi = make_uint4(packh2(h[0], h[1]), packh2(h[2], h[3]),
                              packh2(h[4], h[5]), packh2(h[6], h[7]));
        uint4 lo = make_uint4(packh2(v[0]-h[0], v[1]-h[1]), packh2(v[2]-h[2], v[3]-h[3]),
                              packh2(v[4]-h[4], v[5]-h[5]), packh2(v[6]-h[6], v[7]-h[7]));
        int off = f * 128 + ((chunk ^ (f & 7)) << 4);
        char* base = (char*)g_wimg_0;
        *(uint4*)(base + off)         = hi;
        *(uint4*)(base + 16384 + off) = lo;
        return;
    }
    idx -= 128 * 8;
    if (idx < NN) g_cnt[idx] = 1;   // self-loop
}
#define PREP_ITEMS (NN * 32 + 6 * 128 * 16 + 128 * 8 + NN)

// ---------------- graph preprocessing ---------------------------------------
__global__ void k_count(const void* __restrict__ ei) {
    __shared__ int s64;
    int is64 = sniff_is64(ei, &s64);
    int e = blockIdx.x * blockDim.x + threadIdx.x;
    if (e < EE) atomicAdd(&g_cnt[edge_at2(ei, EE + e, is64)], 1);
}

__global__ void k_scanA() {
    int i = blockIdx.x * 256 + threadIdx.x;
    int v = (i < NN) ? g_cnt[i] : 0;
    __shared__ int sh[8];
    #pragma unroll
    for (int o = 16; o > 0; o >>= 1) v += __shfl_down_sync(0xffffffffu, v, o);
    if ((threadIdx.x & 31) == 0) sh[threadIdx.x >> 5] = v;
    __syncthreads();
    if (threadIdx.x < 8) {
        int t = sh[threadIdx.x];
        #pragma unroll
        for (int o = 4; o > 0; o >>= 1) t += __shfl_down_sync(0xffu, t, o);
        if (threadIdx.x == 0) g_bsum[blockIdx.x] = t;
    }
}

__global__ void k_scanC(int nblk) {
    __shared__ int sh[256];
    __shared__ int sbs[128];
    __shared__ int s_base;
    const int tid = threadIdx.x;
    const int bid = blockIdx.x;
    if (tid < nblk) sbs[tid] = g_bsum[tid];
    __syncthreads();
    if (tid < 32) {
        int p = 0;
        for (int j = tid; j < bid; j += 32) p += sbs[j];
        #pragma unroll
        for (int o = 16; o > 0; o >>= 1) p += __shfl_down_sync(0xffffffffu, p, o);
        if (tid == 0) s_base = p;
    }
    int i = bid * 256 + tid;
    int v = (i < NN) ? g_cnt[i] : 0;
    sh[tid] = v;
    __syncthreads();
    #pragma unroll
    for (int d = 1; d < 256; d <<= 1) {
        int a = (tid >= d) ? sh[tid - d] : 0;
        __syncthreads();
        sh[tid] += a;
        __syncthreads();
    }
    if (i < NN) {
        int excl = sh[tid] - v + s_base;
        g_rowptr[i] = excl;
        g_fill[i]   = excl;
        g_dinv[i]   = rsqrtf((float)v);
        if (i == NN - 1) g_rowptr[NN] = excl + v;
    }
}

__global__ void k_fill(const void* __restrict__ ei) {
    __shared__ int s64;
    int is64 = sniff_is64(ei, &s64);
    int e = blockIdx.x * blockDim.x + threadIdx.x;
    if (e < EE) {
        int s = edge_at2(ei, e, is64);
        int d = edge_at2(ei, EE + e, is64);
        int pos = atomicAdd(&g_fill[d], 1);
        g_csr_src[pos] = s;
        g_csr_w[pos]   = g_dinv[s] * g_dinv[d];
    } else if (e < EN) {
        int i = e - EE;
        int pos = atomicAdd(&g_fill[i], 1);
        float di = g_dinv[i];
        g_csr_src[pos] = i;
        g_csr_w[pos]   = di * di;
    }
}

// ---------------- tensor GEMM: 128 nodes x 128 outs per block ---------------
// A = fp16 (no split), W = fp16 hi/lo planes: D = A*Wh + A*Wl (fp32 accum).
template<int K, bool IN16, bool BIAS, bool OUTACT>
__global__ void __launch_bounds__(256) k_gemm_mma(const void* __restrict__ Hin,
                                                  const unsigned short* __restrict__ Wimg,
                                                  const float* __restrict__ bias,
                                                  __half* __restrict__ outp) {
    extern __shared__ char smem[];
    constexpr int PITCH  = K * 2;
    constexpr int PBYTES = 128 * PITCH;
    constexpr int OFF_A  = 0;
    constexpr int OFF_BH = PBYTES;
    constexpr int OFF_BL = 2 * PBYTES;
    const int tid  = threadIdx.x;
    const int wid  = tid >> 5;
    const int lane = tid & 31;
    const int node0 = blockIdx.x * 128;
    const uint32_t sb = smem_u32(smem);

    {
        const uint4* src = (const uint4*)Wimg;
        uint4* dst = (uint4*)(smem + OFF_BH);
        #pragma unroll
        for (int i = tid; i < 2 * PBYTES / 16; i += 256) dst[i] = src[i];
    }
    {
        constexpr int NCH = K / 8;
        #pragma unroll
        for (int idx = tid; idx < 128 * NCH; idx += 256) {
            int row = idx / NCH;
            int chunk = idx % NCH;
            int node = node0 + row;
            uint4 a16 = make_uint4(0u, 0u, 0u, 0u);
            if (IN16) {
                if (node < NN)
                    a16 = __ldg((const uint4*)Hin + (size_t)node * NCH + chunk);
            } else {
                const float* H = (const float*)Hin;
                float4 v0 = make_float4(0.f, 0.f, 0.f, 0.f), v1 = v0;
                if (node < NN) {
                    v0 = __ldg((const float4*)(H + (size_t)node * K + chunk * 8));
                    v1 = __ldg((const float4*)(H + (size_t)node * K + chunk * 8 + 4));
                }
                a16 = make_uint4(packh2(v0.x, v0.y), packh2(v0.z, v0.w),
                                 packh2(v1.x, v1.y), packh2(v1.z, v1.w));
            }
            int off = row * PITCH + ((chunk ^ (row & 7)) << 4);
            *(uint4*)(smem + OFF_A + off) = a16;
        }
    }
    __syncthreads();

    const int mrow0 = (wid & 3) * 32;
    const int ncol0 = (wid >> 2) * 64;
    float acc[2][8][4] = {};
    const uint32_t aB = sb + OFF_A;
    const uint32_t bOff[2] = {sb + OFF_BH, sb + OFF_BL};

    #pragma unroll
    for (int t = 0; t < 2; t++) {
        const uint32_t bB = bOff[t];
        #pragma unroll
        for (int ks = 0; ks < K / 16; ks++) {
            uint32_t a[2][4], b[8][2];
            #pragma unroll
            for (int i = 0; i < 2; i++) {
                int row = mrow0 + i * 16 + (lane & 15);
                int chunk = ks * 2 + (lane >> 4);
                uint32_t addr = aB + row * PITCH + ((chunk ^ (row & 7)) << 4);
                LDSM_X4(a[i][0], a[i][1], a[i][2], a[i][3], addr);
            }
            #pragma unroll
            for (int p = 0; p < 4; p++) {
                int nrow = ncol0 + p * 16 + (lane >> 4) * 8 + (lane & 7);
                int chunk = ks * 2 + ((lane >> 3) & 1);
                uint32_t addr = bB + nrow * PITCH + ((chunk ^ (nrow & 7)) << 4);
                LDSM_X4(b[2*p][0], b[2*p][1], b[2*p+1][0], b[2*p+1][1], addr);
            }
            #pragma unroll
            for (int i = 0; i < 2; i++)
                #pragma unroll
                for (int j = 0; j < 8; j++)
                    MMA16816F16(acc[i][j], a[i], b[j]);
        }
    }

    #pragma unroll
    for (int i = 0; i < 2; i++) {
        #pragma unroll
        for (int j = 0; j < 8; j++) {
            int c = ncol0 + j * 8 + (lane & 3) * 2;
            float2 bb = make_float2(0.f, 0.f);
            if (BIAS) bb = *(const float2*)(bias + c);
            float e0 = acc[i][j][0] + bb.x, e1 = acc[i][j][1] + bb.y;
            float e2 = acc[i][j][2] + bb.x, e3 = acc[i][j][3] + bb.y;
            if (OUTACT) { e0 = lrelu(e0); e1 = lrelu(e1); e2 = lrelu(e2); e3 = lrelu(e3); }
            int r0 = node0 + mrow0 + i * 16 + (lane >> 2);
            int r1 = r0 + 8;
            if (r0 < NN)
                *(__half2*)(outp + (size_t)r0 * NF + c) = __floats2half2_rn(e0, e1);
            if (r1 < NN)
                *(__half2*)(outp + (size_t)r1 * NF + c) = __floats2half2_rn(e2, e3);
        }
    }
}

// ---------------- aggregation kernels (one warp per node) -------------------
__global__ void k_agg64(float* __restrict__ out) {
    int n = (blockIdx.x * blockDim.x + threadIdx.x) >> 5;
    if (n >= NN) return;
    int lane = threadIdx.x & 31;
    int beg = g_rowptr[n], end = g_rowptr[n + 1];
    const __half2* X = (const __half2*)g_x16;
    float2 acc = make_float2(0.f, 0.f);
    int j = beg;
    for (; j + 3 < end; j += 4) {
        int   s0 = g_csr_src[j],   s1 = g_csr_src[j+1],
              s2 = g_csr_src[j+2], s3 = g_csr_src[j+3];
        float w0 = g_csr_w[j],   w1 = g_csr_w[j+1],
              w2 = g_csr_w[j+2], w3 = g_csr_w[j+3];
        float2 v0 = __half22float2(__ldg(X + s0 * 32 + lane));
        float2 v1 = __half22float2(__ldg(X + s1 * 32 + lane));
        float2 v2 = __half22float2(__ldg(X + s2 * 32 + lane));
        float2 v3 = __half22float2(__ldg(X + s3 * 32 + lane));
        acc.x += w0*v0.x + w1*v1.x + w2*v2.x + w3*v3.x;
        acc.y += w0*v0.y + w1*v1.y + w2*v2.y + w3*v3.y;
    }
    for (; j < end; j++) {
        int s = g_csr_src[j]; float w = g_csr_w[j];
        float2 v = __half22float2(__ldg(X + s * 32 + lane));
        acc.x += w * v.x; acc.y += w * v.y;
    }
    *(float2*)(out + n * 64 + lane * 2) = acc;
}

// 128-dim fp16 gather; epilogue: +bias, leaky, store fp16 hidden state
__global__ void k_agg128(const __half* __restrict__ T, const float* __restrict__ bias,
                         __half* __restrict__ out) {
    int n = (blockIdx.x * blockDim.x + threadIdx.x) >> 5;
    if (n >= NN) return;
    int lane = threadIdx.x & 31;
    int beg = g_rowptr[n], end = g_rowptr[n + 1];
    const uint2* Tv = (const uint2*)T;
    float4 acc = make_float4(0.f, 0.f, 0.f, 0.f);
    int j = beg;
    for (; j + 3 < end; j += 4) {
        int   s0 = g_csr_src[j],   s1 = g_csr_src[j+1],
              s2 = g_csr_src[j+2], s3 = g_csr_src[j+3];
        float w0 = g_csr_w[j],   w1 = g_csr_w[j+1],
              w2 = g_csr_w[j+2], w3 = g_csr_w[j+3];
        uint2 p0 = __ldg(Tv + s0 * 32 + lane);
        uint2 p1 = __ldg(Tv + s1 * 32 + lane);
        uint2 p2 = __ldg(Tv + s2 * 32 + lane);
        uint2 p3 = __ldg(Tv + s3 * 32 + lane);
        float2 a0 = h2f2(p0.x), b0 = h2f2(p0.y);
        float2 a1 = h2f2(p1.x), b1 = h2f2(p1.y);
        float2 a2 = h2f2(p2.x), b2 = h2f2(p2.y);
        float2 a3 = h2f2(p3.x), b3 = h2f2(p3.y);
        acc.x += w0*a0.x + w1*a1.x + w2*a2.x + w3*a3.x;
        acc.y += w0*a0.y + w1*a1.y + w2*a2.y + w3*a3.y;
        acc.z += w0*b0.x + w1*b1.x + w2*b2.x + w3*b3.x;
        acc.w += w0*b0.y + w1*b1.y + w2*b2.y + w3*b3.y;
    }
    for (; j < end; j++) {
        int s = g_csr_src[j]; float w = g_csr_w[j];
        uint2 p = __ldg(Tv + s * 32 + lane);
        float2 a = h2f2(p.x), b = h2f2(p.y);
        acc.x += w*a.x; acc.y += w*a.y; acc.z += w*b.x; acc.w += w*b.y;
    }
    float4 bb = __ldg((const float4*)(bias + lane * 4));
    float e0 = lrelu(acc.x + bb.x), e1 = lrelu(acc.y + bb.y);
    float e2 = lrelu(acc.z + bb.z), e3 = lrelu(acc.w + bb.w);
    uint2 pk = make_uint2(packh2(e0, e1), packh2(e2, e3));
    *(uint2*)(out + (size_t)n * NF + lane * 4) = pk;
}

// last hidden layer: agg + bias + leaky, then FUSED head projection:
// P[n, 0:3] = h[n, :] @ Wout  (warp reduce), written to g_bufA (fp32).
__global__ void k_agg128_head(const __half* __restrict__ T, const float* __restrict__ bias,
                              const float* __restrict__ Wout, float* __restrict__ P) {
    int n = (blockIdx.x * blockDim.x + threadIdx.x) >> 5;
    if (n >= NN) return;
    int lane = threadIdx.x & 31;
    int beg = g_rowptr[n], end = g_rowptr[n + 1];
    const uint2* Tv = (const uint2*)T;
    float4 acc = make_float4(0.f, 0.f, 0.f, 0.f);
    int j = beg;
    for (; j + 3 < end; j += 4) {
        int   s0 = g_csr_src[j],   s1 = g_csr_src[j+1],
              s2 = g_csr_src[j+2], s3 = g_csr_src[j+3];
        float w0 = g_csr_w[j],   w1 = g_csr_w[j+1],
              w2 = g_csr_w[j+2], w3 = g_csr_w[j+3];
        uint2 p0 = __ldg(Tv + s0 * 32 + lane);
        uint2 p1 = __ldg(Tv + s1 * 32 + lane);
        uint2 p2 = __ldg(Tv + s2 * 32 + lane);
        uint2 p3 = __ldg(Tv + s3 * 32 + lane);
        float2 a0 = h2f2(p0.x), b0 = h2f2(p0.y);
        float2 a1 = h2f2(p1.x), b1 = h2f2(p1.y);
        float2 a2 = h2f2(p2.x), b2 = h2f2(p2.y);
        float2 a3 = h2f2(p3.x), b3 = h2f2(p3.y);
        acc.x += w0*a0.x + w1*a1.x + w2*a2.x + w3*a3.x;
        acc.y += w0*a0.y + w1*a1.y + w2*a2.y + w3*a3.y;
        acc.z += w0*b0.x + w1*b1.x + w2*b2.x + w3*b3.x;
        acc.w += w0*b0.y + w1*b1.y + w2*b2.y + w3*b3.y;
    }
    for (; j < end; j++) {
        int s = g_csr_src[j]; float w = g_csr_w[j];
        uint2 p = __ldg(Tv + s * 32 + lane);
        float2 a = h2f2(p.x), b = h2f2(p.y);
        acc.x += w*a.x; acc.y += w*a.y; acc.z += w*b.x; acc.w += w*b.y;
    }
    float4 bb = __ldg((const float4*)(bias + lane * 4));
    float hv[4];
    hv[0] = lrelu(acc.x + bb.x); hv[1] = lrelu(acc.y + bb.y);
    hv[2] = lrelu(acc.z + bb.z); hv[3] = lrelu(acc.w + bb.w);
    // head projection: this lane owns features k = lane*4 .. lane*4+3
    float a0 = 0.f, a1 = 0.f, a2 = 0.f;
    #pragma unroll
    for (int q = 0; q < 4; q++) {
        int k = lane * 4 + q;
        a0 += hv[q] * __ldg(Wout + k * 3 + 0);
        a1 += hv[q] * __ldg(Wout + k * 3 + 1);
        a2 += hv[q] * __ldg(Wout + k * 3 + 2);
    }
    #pragma unroll
    for (int o = 16; o > 0; o >>= 1) {
        a0 += __shfl_down_sync(0xffffffffu, a0, o);
        a1 += __shfl_down_sync(0xffffffffu, a1, o);
        a2 += __shfl_down_sync(0xffffffffu, a2, o);
    }
    if (lane == 0) {
        P[n * 3 + 0] = a0;
        P[n * 3 + 1] = a1;
        P[n * 3 + 2] = a2;
    }
}

__global__ void k_agg3(const float* __restrict__ T, const float* __restrict__ bout,
                       float* __restrict__ out) {
    int n = (blockIdx.x * blockDim.x + threadIdx.x) >> 5;
    if (n >= NN) return;
    int lane = threadIdx.x & 31;
    int beg = g_rowptr[n], end = g_rowptr[n + 1];
    float a0 = 0.f, a1 = 0.f, a2 = 0.f;
    for (int j = beg + lane; j < end; j += 32) {
        int s = g_csr_src[j]; float w = g_csr_w[j];
        a0 += w * __ldg(T + s * 3 + 0);
        a1 += w * __ldg(T + s * 3 + 1);
        a2 += w * __ldg(T + s * 3 + 2);
    }
    #pragma unroll
    for (int o = 16; o > 0; o >>= 1) {
        a0 += __shfl_down_sync(0xffffffffu, a0, o);
        a1 += __shfl_down_sync(0xffffffffu, a1, o);
        a2 += __shfl_down_sync(0xffffffffu, a2, o);
    }
    if (lane == 0) {
        out[n * 3 + 0] = tanhf(a0 + __ldg(bout + 0)) * 0.5f;
        out[n * 3 + 1] = tanhf(a1 + __ldg(bout + 1)) * 0.5f;
        out[n * 3 + 2] = tanhf(a2 + __ldg(bout + 2)) * 0.5f;
    }
}

// ---------------- launch -----------------------------------------------------
extern "C" void kernel_launch(void* const* d_in, const int* in_sizes, int n_in,
                              void* d_out, int out_size) {
    const float* x    = (const float*)d_in[0];
    const void*  ei   = d_in[1];
    const float* W0   = (const float*)d_in[2];
    const float* b0   = (const float*)d_in[3];
    const float* Wh   = (const float*)d_in[4];
    const float* bh   = (const float*)d_in[5];
    const float* Wout = (const float*)d_in[6];
    const float* bout = (const float*)d_in[7];
    float* out = (float*)d_out;

    void *pA, *pH, *pM, *pWh, *pW0;
    cudaGetSymbolAddress(&pA, g_bufA);
    cudaGetSymbolAddress(&pH, g_bufH);
    cudaGetSymbolAddress(&pM, g_bufM);
    cudaGetSymbolAddress(&pWh, g_wimg_h);
    cudaGetSymbolAddress(&pW0, g_wimg_0);
    float* A = (float*)pA;
    __half* H16 = (__half*)pH;
    __half* M16 = (__half*)pM;
    const unsigned short* WIH = (const unsigned short*)pWh;
    const unsigned short* WI0 = (const unsigned short*)pW0;

    const int SM128 = 3 * 128 * 128 * 2;  // 96 KB (A + Wh + Wl)
    const int SM64  = 3 * 128 * 64 * 2;   // 48 KB
    cudaFuncSetAttribute((const void*)k_gemm_mma<128, true, false, false>,
                         cudaFuncAttributeMaxDynamicSharedMemorySize, SM128);
    cudaFuncSetAttribute((const void*)k_gemm_mma<64, false, true, true>,
                         cudaFuncAttributeMaxDynamicSharedMemorySize, SM64);

    const int scanBlocks = (NN + 255) / 256;  // 118

    k_prep<<<(PREP_ITEMS + 255) / 256, 256>>>(x, Wh, W0);
    k_count<<<(EE + 255) / 256, 256>>>(ei);
    k_scanA<<<scanBlocks, 256>>>();
    k_scanC<<<scanBlocks, 256>>>(scanBlocks);
    k_fill<<<(EN + 255) / 256, 256>>>(ei);

    const int warpBlocks = (NN * 32 + 255) / 256;   // one warp per node
    const int tcBlocks   = (NN + 127) / 128;        // 235

    // layer 0:  H16 = leaky( (A x) @ W0 + b0 )   (fp16, pre-activated)
    k_agg64<<<warpBlocks, 256>>>(A);
    k_gemm_mma<64, false, true, true><<<tcBlocks, 256, SM64>>>(A, WI0, b0, H16);

    // hidden layers 0..4: M16 = H16 @ Wh[i];  H16 = leaky( A·M16 + bh[i] )
    for (int i = 0; i < 5; i++) {
        k_gemm_mma<128, true, false, false><<<tcBlocks, 256, SM128>>>(
            H16, WIH + (size_t)i * 32768, nullptr, M16);
        k_agg128<<<warpBlocks, 256>>>(M16, bh + (size_t)i * NF, H16);
    }
    // hidden layer 5 with fused head: P = leaky(A·M16 + bh[5]) @ Wout
    k_gemm_mma<128, true, false, false><<<tcBlocks, 256, SM128>>>(
        H16, WIH + (size_t)5 * 32768, nullptr, M16);
    k_agg128_head<<<warpBlocks, 256>>>(M16, bh + (size_t)5 * NF, Wout, A);

    // out = tanh( A P + bout ) * 0.5
    k_agg3<<<warpBlocks, 256>>>(A, bout, out);
}